// round 16
// baseline (speedup 1.0000x reference)
#include <cuda.h>
#include <cuda_runtime.h>
#include <cuda_bf16.h>
#include <cuda_fp16.h>
#include <math.h>
#include <stdint.h>

#define B_  128
#define C_  1024
#define H_  24
#define W_  24
#define N_  576
#define NH  8
#define HD  128
#define QH  12
#define QW  12
#define QN  144
#define BH  (B_*NH)

// ---------------- fp32 scratch ----------------
__device__ float g_q   [(size_t)B_*QN*C_];
__device__ float g_relh[(size_t)BH*QN*H_];
__device__ float g_relw[(size_t)BH*QN*W_];
// fp16 operands (all single precision fp16 now)
__device__ __half g_axs[(size_t)B_*N_*C_];      // fp16(x), transposed
__device__ __half g_aqs[(size_t)B_*QN*C_];      // fp16(pooled x)
__device__ __half g_aos[(size_t)B_*QN*C_];      // fp16(o)
// TRANSPOSED weights [N,K], single fp16
__device__ __half g_wq2[(size_t)C_*C_];
__device__ __half g_wk2[(size_t)C_*C_];
__device__ __half g_wv2[(size_t)C_*C_];
__device__ __half g_wp2[(size_t)C_*C_];
// head-major fp16 tensors
__device__ __half g_qs [(size_t)BH*QN*HD];
__device__ __half g_k2 [(size_t)BH*N_*HD];
__device__ __half g_v2 [(size_t)BH*N_*HD];
__device__ __half g_ps [(size_t)BH*QN*N_];

// ---------------- helpers ----------------
__device__ __forceinline__ uint32_t smem_u32(const void* p) {
    return (uint32_t)__cvta_generic_to_shared(p);
}
__device__ __forceinline__ uint32_t swz(uint32_t o) {
    return o ^ ((o >> 3) & 0x70);
}

#define MMA_F16(ACC, A, B0, B1)                                               \
    asm volatile(                                                             \
        "mma.sync.aligned.m16n8k16.row.col.f32.f16.f16.f32 "                  \
        "{%0,%1,%2,%3}, {%4,%5,%6,%7}, {%8,%9}, {%0,%1,%2,%3};"               \
        : "+f"((ACC)[0]), "+f"((ACC)[1]), "+f"((ACC)[2]), "+f"((ACC)[3])      \
        : "r"((A)[0]), "r"((A)[1]), "r"((A)[2]), "r"((A)[3]),                 \
          "r"(B0), "r"(B1))

#define LDSM_X4(R, ADDR)                                                      \
    asm volatile("ldmatrix.sync.aligned.m8n8.x4.shared.b16 {%0,%1,%2,%3}, [%4];" \
                 : "=r"((R)[0]), "=r"((R)[1]), "=r"((R)[2]), "=r"((R)[3]) : "r"(ADDR))
#define LDSM_X4T(R, ADDR)                                                     \
    asm volatile("ldmatrix.sync.aligned.m8n8.x4.trans.shared.b16 {%0,%1,%2,%3}, [%4];" \
                 : "=r"((R)[0]), "=r"((R)[1]), "=r"((R)[2]), "=r"((R)[3]) : "r"(ADDR))

#define MBAR_INIT(mb, cnt) \
    asm volatile("mbarrier.init.shared.b64 [%0], %1;" :: "r"(mb), "r"((uint32_t)(cnt)) : "memory")
#define MBAR_EXPECT_TX(mb, bytes) \
    asm volatile("mbarrier.arrive.expect_tx.shared.b64 _, [%0], %1;" :: "r"(mb), "r"((uint32_t)(bytes)) : "memory")
#define MBAR_ARRIVE(mb) \
    asm volatile("mbarrier.arrive.shared.b64 _, [%0];" :: "r"(mb) : "memory")
#define MBAR_WAIT(mb, ph) do {                                                    \
    asm volatile("{\n\t.reg .pred P1;\n\t"                                        \
        "WAIT_LOOP_%=:\n\t"                                                       \
        "mbarrier.try_wait.parity.acquire.cta.shared::cta.b64 P1, [%0], %1, 0x989680;\n\t" \
        "@P1 bra.uni WAIT_DONE_%=;\n\t"                                           \
        "bra.uni WAIT_LOOP_%=;\n\t"                                               \
        "WAIT_DONE_%=:\n\t}"                                                      \
        :: "r"(mb), "r"((uint32_t)(ph)) : "memory");                              \
} while(0)

#define TMA_LOAD_2D(sa, map, cx, cy, mb)                                          \
    asm volatile("cp.async.bulk.tensor.2d.shared::cta.global.tile.mbarrier::complete_tx::bytes " \
        "[%0], [%1, {%2, %3}], [%4];"                                             \
        :: "r"(sa), "l"(map), "r"((int32_t)(cx)), "r"((int32_t)(cy)), "r"(mb) : "memory")

// ---------------- conversions ----------------
__global__ __launch_bounds__(256) void split_wT_f16_kernel(const float* __restrict__ W,
                                                           __half* __restrict__ WT) {
    __shared__ float t[32][33];
    int k0 = blockIdx.x * 32, n0 = blockIdx.y * 32;
    int tx = threadIdx.x, ty = threadIdx.y;
    #pragma unroll
    for (int i = 0; i < 4; i++)
        t[ty + i * 8][tx] = W[(size_t)(k0 + ty + i * 8) * C_ + n0 + tx];
    __syncthreads();
    #pragma unroll
    for (int i = 0; i < 4; i++)
        WT[(size_t)(n0 + ty + i * 8) * C_ + k0 + tx] = __float2half(t[tx][ty + i * 8]);
}

__global__ __launch_bounds__(256) void conv_x_kernel(const float* __restrict__ x) {
    __shared__ float tile[32][33];
    int b  = blockIdx.z;
    int n0 = blockIdx.x * 32;
    int c0 = blockIdx.y * 32;
    int tx = threadIdx.x, ty = threadIdx.y;
    const float* xb = x + (size_t)b * C_ * N_;
    #pragma unroll
    for (int i = 0; i < 4; i++)
        tile[ty + i * 8][tx] = xb[(size_t)(c0 + ty + i * 8) * N_ + n0 + tx];
    __syncthreads();
    #pragma unroll
    for (int i = 0; i < 4; i++) {
        int n = n0 + ty + i * 8;
        g_axs[((size_t)b * N_ + n) * C_ + c0 + tx] = __float2half(tile[tx][ty + i * 8]);
    }
}

// ---------------- avg-pool -> single fp16 ----------------
__global__ __launch_bounds__(256) void pool_kernel(const float* __restrict__ x) {
    __shared__ float sp[16][577];
    int b  = blockIdx.y;
    int c0 = blockIdx.x * 16;
    int tid = threadIdx.x;
    const float* xb = x + (size_t)b * C_ * N_ + (size_t)c0 * N_;
    #pragma unroll
    for (int r = 0; r < 36; r++) {
        int idx = tid + r * 256;
        int p = idx / 576, n = idx - p * 576;
        sp[p][n] = xb[(size_t)p * N_ + n];
    }
    __syncthreads();
    #pragma unroll
    for (int r = 0; r < 9; r++) {
        int idx = tid + r * 256;
        int qn = idx >> 4, cl = idx & 15;
        int qy = qn / 12, qx = qn - qy * 12;
        float s = 0.f;
        #pragma unroll
        for (int dy = -1; dy <= 1; dy++) {
            int y = 2 * qy + dy;
            if ((unsigned)y < 24u) {
                #pragma unroll
                for (int dx = -1; dx <= 1; dx++) {
                    int xx = 2 * qx + dx;
                    if ((unsigned)xx < 24u) s += sp[cl][y * 24 + xx];
                }
            }
        }
        g_aqs[((size_t)b * QN + qn) * C_ + c0 + cl] = __float2half(s * (1.0f / 9.0f));
    }
}

// ---------------- single-term GEMM: C = A·B ----------------
// mode 1: fp32 NCHW scatter + bias.  mode 2: single fp16 head-major.  mode 3: mode2 + fp32 row-major.
#define G1_TILE  16384
#define G1_BUF   (2*G1_TILE)
#define G1_SMEM  (3*G1_BUF + 1024)
#define NSTAGE   16

__global__ __launch_bounds__(512) void gemm_1t(
    const __grid_constant__ CUtensorMap tmA,
    const __grid_constant__ CUtensorMap tmBa,
    const __grid_constant__ CUtensorMap tmBb,
    __half* __restrict__ Da,
    __half* __restrict__ Db,
    const float* __restrict__ bias,
    float* __restrict__ Cm,
    int rpb, int mode)
{
    extern __shared__ char smem[];
    uint32_t sraw = smem_u32(smem);
    uint32_t fullb[3]  = {sraw, sraw + 8, sraw + 16};
    uint32_t emptyb[3] = {sraw + 24, sraw + 32, sraw + 40};
    uint32_t tiles = (sraw + 64 + 1023) & ~1023u;

    int tid = threadIdx.x, lane = tid & 31, warp = tid >> 5;
    int wm = warp >> 2, wn = warp & 3;
    int rowBase = blockIdx.y * 128;
    int colBase = blockIdx.x * 128;
    const CUtensorMap* pB = blockIdx.z ? &tmBb : &tmBa;
    __half* Ds = blockIdx.z ? Db : Da;

    if (tid == 0) {
        MBAR_INIT(fullb[0], 1);  MBAR_INIT(fullb[1], 1);  MBAR_INIT(fullb[2], 1);
        MBAR_INIT(emptyb[0], 512); MBAR_INIT(emptyb[1], 512); MBAR_INIT(emptyb[2], 512);
    }
    __syncthreads();

    float acc[2][4][4];
    #pragma unroll
    for (int i = 0; i < 2; i++)
        #pragma unroll
        for (int j = 0; j < 4; j++)
            #pragma unroll
            for (int r = 0; r < 4; r++) acc[i][j][r] = 0.f;

    int phF[3] = {0, 0, 0};
    int phE[3] = {0, 0, 0};
    auto issue = [&](int s, int slot) {
        uint32_t base = tiles + slot * G1_BUF;
        MBAR_EXPECT_TX(fullb[slot], G1_BUF);
        int k0 = s * 64;
        TMA_LOAD_2D(base,           &tmA, k0, rowBase, fullb[slot]);
        TMA_LOAD_2D(base + G1_TILE, pB,   k0, colBase, fullb[slot]);
    };
    if (tid == 0) { issue(0, 0); issue(1, 1); issue(2, 2); }

    uint32_t ah[2][2][4], bf[2][2][4];
    int arow0 = wm * 32 + (lane & 7) + ((lane >> 3) & 1) * 8;
    int acol8 = (lane >> 4) << 3;
    int brow0 = wn * 32 + (lane & 7) + ((lane >> 4) & 1) * 8;
    int bcol8 = (lane >> 3) & 1 ? 8 : 0;

    for (int s = 0; s < NSTAGE; s++) {
        int slot = s % 3;
        MBAR_WAIT(fullb[slot], phF[slot]); phF[slot] ^= 1;
        uint32_t aA = tiles + slot * G1_BUF;
        uint32_t bB = aA + G1_TILE;
        {
            #pragma unroll
            for (int mf = 0; mf < 2; mf++) {
                uint32_t off = swz((uint32_t)((arow0 + mf * 16) * 128 + acol8 * 2));
                LDSM_X4(ah[0][mf], aA + off);
            }
            #pragma unroll
            for (int g = 0; g < 2; g++) {
                uint32_t off = swz((uint32_t)((brow0 + g * 16) * 128 + bcol8 * 2));
                LDSM_X4(bf[0][g], bB + off);
            }
        }
        #pragma unroll
        for (int kki = 0; kki < 4; kki++) {
            int pb = kki & 1;
            if (kki < 3) {
                int nb = pb ^ 1;
                int kk = (kki + 1) * 16;
                #pragma unroll
                for (int mf = 0; mf < 2; mf++) {
                    uint32_t off = swz((uint32_t)((arow0 + mf * 16) * 128 + (kk + acol8) * 2));
                    LDSM_X4(ah[nb][mf], aA + off);
                }
                #pragma unroll
                for (int g = 0; g < 2; g++) {
                    uint32_t off = swz((uint32_t)((brow0 + g * 16) * 128 + (kk + bcol8) * 2));
                    LDSM_X4(bf[nb][g], bB + off);
                }
            }
            #pragma unroll
            for (int mf = 0; mf < 2; mf++)
                #pragma unroll
                for (int nf = 0; nf < 4; nf++) {
                    uint32_t b0 = bf[pb][nf >> 1][(nf & 1) * 2 + 0];
                    uint32_t b1 = bf[pb][nf >> 1][(nf & 1) * 2 + 1];
                    MMA_F16(acc[mf][nf], ah[pb][mf], b0, b1);
                }
        }
        MBAR_ARRIVE(emptyb[slot]);
        if (tid == 0 && s + 3 < NSTAGE) {
            MBAR_WAIT(emptyb[slot], phE[slot]); phE[slot] ^= 1;
            issue(s + 3, slot);
        }
    }

    int gid = lane >> 2, tig = lane & 3;
    #pragma unroll
    for (int mf = 0; mf < 2; mf++)
        #pragma unroll
        for (int nf = 0; nf < 4; nf++) {
            int c0 = colBase + wn * 32 + nf * 8 + tig * 2;
            #pragma unroll
            for (int rr = 0; rr < 2; rr++) {
                int row = rowBase + wm * 32 + mf * 16 + gid + rr * 8;
                float v0 = acc[mf][nf][rr * 2 + 0];
                float v1 = acc[mf][nf][rr * 2 + 1];
                if (mode == 1) {
                    int bq = row / QN, qi = row - bq * QN;
                    Cm[((size_t)bq * C_ + c0) * QN + qi]     = v0 + bias[c0];
                    Cm[((size_t)bq * C_ + c0 + 1) * QN + qi] = v1 + bias[c0 + 1];
                } else {
                    int b = row / rpb, n = row - b * rpb;
                    int h = c0 >> 7, d = c0 & 127;
                    size_t di = (((size_t)b * NH + h) * rpb + n) * HD + d;
                    *(__half2*)(Ds + di) = __floats2half2_rn(v0, v1);
                    if (mode == 3)
                        *(float2*)&Cm[(size_t)row * C_ + c0] = make_float2(v0, v1);
                }
            }
        }
}

// ---------------- relative position bias dots ----------------
__global__ __launch_bounds__(64) void relpos_kernel(const float* __restrict__ rel_h,
                                                    const float* __restrict__ rel_w) {
    int gid = blockIdx.x;
    int bh = gid / QN, i = gid - bh * QN;
    int b = bh >> 3, h = bh & 7;
    int qy = i / 12, qx = i - qy * 12;
    int t = threadIdx.x;
    const float* qrow = g_q + ((size_t)b * QN + i) * C_ + h * HD;
    if (t < 24) {
        const float* R = rel_h + (size_t)(2 * qy - t + 23) * HD;
        float a0 = 0, a1 = 0, a2 = 0, a3 = 0;
        #pragma unroll
        for (int d = 0; d < HD; d += 4) {
            a0 += qrow[d + 0] * R[d + 0];
            a1 += qrow[d + 1] * R[d + 1];
            a2 += qrow[d + 2] * R[d + 2];
            a3 += qrow[d + 3] * R[d + 3];
        }
        g_relh[(size_t)gid * 24 + t] = (a0 + a1) + (a2 + a3);
    } else if (t >= 32 && t < 56) {
        int kx = t - 32;
        const float* R = rel_w + (size_t)(2 * qx - kx + 23) * HD;
        float a0 = 0, a1 = 0, a2 = 0, a3 = 0;
        #pragma unroll
        for (int d = 0; d < HD; d += 4) {
            a0 += qrow[d + 0] * R[d + 0];
            a1 += qrow[d + 1] * R[d + 1];
            a2 += qrow[d + 2] * R[d + 2];
            a3 += qrow[d + 3] * R[d + 3];
        }
        g_relw[(size_t)gid * 24 + kx] = (a0 + a1) + (a2 + a3);
    }
}

// ---------------- FUSED QK^T + bias + softmax -> single fp16 P ----------------
#define QKF_Q    0
#define QKF_K0   12288
#define QKF_KBUF 24576
#define QKF_REL  (12288 + 2*24576)
#define QKF_RED  (QKF_REL + 9216)
#define QKF_SMEM (QKF_RED + 2304 + 1088)

__global__ __launch_bounds__(576) void qk_fused(
    const __grid_constant__ CUtensorMap tmQ,
    const __grid_constant__ CUtensorMap tmK)
{
    extern __shared__ char smem[];
    uint32_t sraw = smem_u32(smem);
    uint32_t fullb[2]  = {sraw, sraw + 8};
    uint32_t emptyb[2] = {sraw + 16, sraw + 24};
    uint32_t tiles = (sraw + 64 + 1023) & ~1023u;
    char* tilesp = smem + (tiles - sraw);
    float* srelh = (float*)(tilesp + QKF_REL);
    float* srelw = srelh + 48 * 24;
    float* smax  = (float*)(tilesp + QKF_RED);
    float* ssum  = smax + 48 * 6;

    int bh = blockIdx.z;
    int rowBase = blockIdx.y * 48;
    int tid = threadIdx.x, lane = tid & 31, warp = tid >> 5;
    int wm = warp / 6, wn = warp % 6;
    int gid = lane >> 2, tig = lane & 3;

    if (tid == 0) {
        MBAR_INIT(fullb[0], 1);  MBAR_INIT(fullb[1], 1);
        MBAR_INIT(emptyb[0], 576); MBAR_INIT(emptyb[1], 576);
    }
    __syncthreads();

    for (int idx = tid; idx < 48 * 24; idx += 576) {
        size_t gidx = ((size_t)bh * QN + rowBase + idx / 24) * 24 + (idx % 24);
        srelh[idx] = g_relh[gidx];
        srelw[idx] = g_relw[gidx];
    }

    int phF[2] = {0, 0}, phE[2] = {0, 0};
    auto issue = [&](int c, int buf) {
        uint32_t kb = tiles + QKF_K0 + buf * QKF_KBUF;
        MBAR_EXPECT_TX(fullb[buf], (c == 0) ? (12288u + QKF_KBUF) : (uint32_t)QKF_KBUF);
        int ky0 = bh * N_ + c * 96;
        if (c == 0) {
            int qy = bh * QN + rowBase;
            TMA_LOAD_2D(tiles + QKF_Q,        &tmQ, 0,  qy, fullb[0]);
            TMA_LOAD_2D(tiles + QKF_Q + 6144, &tmQ, 64, qy, fullb[0]);
        }
        TMA_LOAD_2D(kb,         &tmK, 0,  ky0, fullb[buf]);
        TMA_LOAD_2D(kb + 12288, &tmK, 64, ky0, fullb[buf]);
    };
    if (tid == 0) { issue(0, 0); issue(1, 1); }

    float acc[12][4];
    #pragma unroll
    for (int j = 0; j < 12; j++)
        #pragma unroll
        for (int r = 0; r < 4; r++) acc[j][r] = 0.f;

    int arow = wm * 16 + (lane & 7) + ((lane >> 3) & 1) * 8;
    int acol8 = (lane >> 4) << 3;
    int brow = wn * 16 + (lane & 7) + ((lane >> 4) & 1) * 8;
    int bcol8 = ((lane >> 3) & 1) * 8;

    for (int c = 0; c < 6; c++) {
        int buf = c & 1;
        MBAR_WAIT(fullb[buf], phF[buf]); phF[buf] ^= 1;
        uint32_t kB = tiles + QKF_K0 + buf * QKF_KBUF;

        #pragma unroll
        for (int kk = 0; kk < 128; kk += 16) {
            uint32_t a_[4];
            {
                int ce = kk + acol8;
                uint32_t off = (uint32_t)((ce >> 6) * 6144) + swz((uint32_t)(arow * 128 + (ce & 63) * 2));
                LDSM_X4(a_, tiles + QKF_Q + off);
            }
            uint32_t b_[4];
            {
                int kc = kk + bcol8;
                uint32_t off = (uint32_t)((kc >> 6) * 12288) + swz((uint32_t)(brow * 128 + (kc & 63) * 2));
                LDSM_X4(b_, kB + off);
            }
            #pragma unroll
            for (int j = 0; j < 2; j++) {
                float* A = acc[c * 2 + j];
                MMA_F16(A, a_, b_[j * 2], b_[j * 2 + 1]);
            }
        }
        MBAR_ARRIVE(emptyb[buf]);
        if (tid == 0 && c + 2 < 6) {
            MBAR_WAIT(emptyb[buf], phE[buf]); phE[buf] ^= 1;
            issue(c + 2, buf);
        }
    }
    __syncthreads();

    const float scale = 0.08838834764831845f;
    int il0 = wm * 16 + gid;
    float mrow[2] = {-1e30f, -1e30f};
    #pragma unroll
    for (int nf = 0; nf < 12; nf++) {
        int colb = (nf >> 1) * 96 + wn * 16 + (nf & 1) * 8 + tig * 2;
        #pragma unroll
        for (int rr = 0; rr < 2; rr++) {
            int il = il0 + rr * 8;
            #pragma unroll
            for (int cc = 0; cc < 2; cc++) {
                int col = colb + cc;
                int ky = col / 24, kx = col - ky * 24;
                float v = acc[nf][rr * 2 + cc] * scale + srelh[il * 24 + ky] + srelw[il * 24 + kx];
                acc[nf][rr * 2 + cc] = v;
                mrow[rr] = fmaxf(mrow[rr], v);
            }
        }
    }
    #pragma unroll
    for (int o = 1; o <= 2; o <<= 1) {
        mrow[0] = fmaxf(mrow[0], __shfl_xor_sync(0xffffffffu, mrow[0], o));
        mrow[1] = fmaxf(mrow[1], __shfl_xor_sync(0xffffffffu, mrow[1], o));
    }
    if (tig == 0) {
        smax[(il0) * 6 + wn] = mrow[0];
        smax[(il0 + 8) * 6 + wn] = mrow[1];
    }
    __syncthreads();
    float M[2];
    #pragma unroll
    for (int rr = 0; rr < 2; rr++) {
        const float* r = smax + (il0 + rr * 8) * 6;
        M[rr] = fmaxf(fmaxf(fmaxf(r[0], r[1]), fmaxf(r[2], r[3])), fmaxf(r[4], r[5]));
    }
    float srow[2] = {0.f, 0.f};
    #pragma unroll
    for (int nf = 0; nf < 12; nf++)
        #pragma unroll
        for (int rr = 0; rr < 2; rr++)
            #pragma unroll
            for (int cc = 0; cc < 2; cc++) {
                float e = __expf(acc[nf][rr * 2 + cc] - M[rr]);
                acc[nf][rr * 2 + cc] = e;
                srow[rr] += e;
            }
    #pragma unroll
    for (int o = 1; o <= 2; o <<= 1) {
        srow[0] += __shfl_xor_sync(0xffffffffu, srow[0], o);
        srow[1] += __shfl_xor_sync(0xffffffffu, srow[1], o);
    }
    if (tig == 0) {
        ssum[(il0) * 6 + wn] = srow[0];
        ssum[(il0 + 8) * 6 + wn] = srow[1];
    }
    __syncthreads();
    float inv[2];
    #pragma unroll
    for (int rr = 0; rr < 2; rr++) {
        const float* r = ssum + (il0 + rr * 8) * 6;
        inv[rr] = 1.0f / ((r[0] + r[1]) + (r[2] + r[3]) + (r[4] + r[5]));
    }
    #pragma unroll
    for (int nf = 0; nf < 12; nf++) {
        int colb = (nf >> 1) * 96 + wn * 16 + (nf & 1) * 8 + tig * 2;
        #pragma unroll
        for (int rr = 0; rr < 2; rr++) {
            size_t off = ((size_t)bh * QN + rowBase + il0 + rr * 8) * N_ + colb;
            *(__half2*)(g_ps + off) = __floats2half2_rn(acc[nf][rr * 2 + 0] * inv[rr],
                                                        acc[nf][rr * 2 + 1] * inv[rr]);
        }
    }
}

// ---------------- AV mma (single P, single V) -> single fp16 o (+q residual) ----------------
#define AV_P    0
#define AV_V    6144
#define AV_BUF  22528
#define AV_SMEM (2*AV_BUF + 2048)

__global__ __launch_bounds__(384) void av_mma(
    const __grid_constant__ CUtensorMap tmP,
    const __grid_constant__ CUtensorMap tmV)
{
    extern __shared__ char smem[];
    uint32_t sraw = smem_u32(smem);
    uint32_t fullb[2]  = {sraw, sraw + 8};
    uint32_t emptyb[2] = {sraw + 16, sraw + 24};
    uint32_t tiles = (sraw + 64 + 1023) & ~1023u;

    int bh = blockIdx.z;
    int b = bh >> 3, h = bh & 7;
    int rowBase = blockIdx.y * 48;
    int tid = threadIdx.x, lane = tid & 31, warp = tid >> 5;
    int wm = warp >> 2, wn = warp & 3;
    int nBase = wn * 32;

    if (tid == 0) {
        MBAR_INIT(fullb[0], 1);  MBAR_INIT(fullb[1], 1);
        MBAR_INIT(emptyb[0], 384); MBAR_INIT(emptyb[1], 384);
    }
    __syncthreads();

    float acc[4][4];
    #pragma unroll
    for (int j = 0; j < 4; j++)
        #pragma unroll
        for (int r = 0; r < 4; r++) acc[j][r] = 0.f;

    int phF[2] = {0, 0};
    int phE[2] = {1, 1};

    auto issue = [&](int s, int buf) {
        uint32_t base = tiles + buf * AV_BUF;
        MBAR_EXPECT_TX(fullb[buf], AV_BUF);
        int k0 = s * 64;
        int py = bh * QN + rowBase;
        int vy = bh * N_ + k0;
        TMA_LOAD_2D(base + AV_P, &tmP, k0, py, fullb[buf]);
        TMA_LOAD_2D(base + AV_V,        &tmV, 0,  vy, fullb[buf]);
        TMA_LOAD_2D(base + AV_V + 8192, &tmV, 64, vy, fullb[buf]);
    };

    if (tid == 0) {
        MBAR_WAIT(emptyb[0], phE[0]); phE[0] ^= 1;
        issue(0, 0);
    }

    for (int s = 0; s < 9; s++) {
        int buf = s & 1;
        if (tid == 0 && s + 1 < 9) {
            int nb = buf ^ 1;
            MBAR_WAIT(emptyb[nb], phE[nb]); phE[nb] ^= 1;
            issue(s + 1, nb);
        }
        MBAR_WAIT(fullb[buf], phF[buf]); phF[buf] ^= 1;
        uint32_t base = tiles + buf * AV_BUF;

        #pragma unroll
        for (int kk = 0; kk < 64; kk += 16) {
            uint32_t ap[4];
            {
                int row = wm * 16 + (lane & 7) + ((lane >> 3) & 1) * 8;
                int ce  = kk + ((lane >> 4) << 3);
                uint32_t off = swz((uint32_t)(row * 128 + ce * 2));
                LDSM_X4(ap, base + AV_P + off);
            }
            uint32_t bvf[2][4];
            #pragma unroll
            for (int g = 0; g < 2; g++) {
                int vrow = kk + (lane & 15);
                int d    = nBase + g * 16 + ((lane >> 4) << 3);
                uint32_t off = (uint32_t)((d >> 6) * 8192) + swz((uint32_t)(vrow * 128 + (d & 63) * 2));
                LDSM_X4T(bvf[g], base + AV_V + off);
            }
            #pragma unroll
            for (int nf = 0; nf < 4; nf++) {
                uint32_t b0 = bvf[nf >> 1][(nf & 1) * 2 + 0];
                uint32_t b1 = bvf[nf >> 1][(nf & 1) * 2 + 1];
                MMA_F16(acc[nf], ap, b0, b1);
            }
        }
        MBAR_ARRIVE(emptyb[buf]);
    }

    int gid = lane >> 2, tig = lane & 3;
    #pragma unroll
    for (int nf = 0; nf < 4; nf++) {
        int d = nBase + nf * 8 + tig * 2;
        #pragma unroll
        for (int rr = 0; rr < 2; rr++) {
            int i = rowBase + wm * 16 + gid + rr * 8;
            size_t off = ((size_t)b * QN + i) * C_ + h * HD + d;
            float2 qv = *(const float2*)(g_q + off);
            *(__half2*)(g_aos + off) = __floats2half2_rn(acc[nf][rr * 2 + 0] + qv.x,
                                                         acc[nf][rr * 2 + 1] + qv.y);
        }
    }
}

// ---------------- host: tensormap builder ----------------
typedef CUresult (*EncodeTiledFn)(CUtensorMap*, CUtensorMapDataType, cuuint32_t, void*,
                                  const cuuint64_t*, const cuuint64_t*, const cuuint32_t*,
                                  const cuuint32_t*, CUtensorMapInterleave, CUtensorMapSwizzle,
                                  CUtensorMapL2promotion, CUtensorMapFloatOOBfill);

static void make_map(EncodeTiledFn enc, CUtensorMap* m, void* ptr,
                     uint64_t dim0, uint64_t rows, uint32_t box0, uint32_t box1) {
    cuuint64_t dims[2]    = {(cuuint64_t)dim0, (cuuint64_t)rows};
    cuuint64_t strides[1] = {(cuuint64_t)dim0 * 2};
    cuuint32_t box[2]     = {box0, box1};
    cuuint32_t es[2]      = {1, 1};
    enc(m, CU_TENSOR_MAP_DATA_TYPE_FLOAT16, 2, ptr, dims, strides, box, es,
        CU_TENSOR_MAP_INTERLEAVE_NONE, CU_TENSOR_MAP_SWIZZLE_128B,
        CU_TENSOR_MAP_L2_PROMOTION_L2_128B, CU_TENSOR_MAP_FLOAT_OOB_FILL_NONE);
}

// ---------------- launch ----------------
extern "C" void kernel_launch(void* const* d_in, const int* in_sizes, int n_in,
                              void* d_out, int out_size) {
    const float* x   = (const float*)d_in[0];
    const float* Wq  = (const float*)d_in[1];
    const float* Wk  = (const float*)d_in[2];
    const float* Wv  = (const float*)d_in[3];
    const float* Wp  = (const float*)d_in[4];
    const float* bp  = (const float*)d_in[5];
    const float* rph = (const float*)d_in[6];
    const float* rpw = (const float*)d_in[7];
    float* out = (float*)d_out;

    float *q;
    __half *axs, *aqs, *aos;
    __half *wq2, *wk2, *wv2, *wp2;
    __half *qs, *k2, *v2, *ps;
    cudaGetSymbolAddress((void**)&q,  g_q);
    cudaGetSymbolAddress((void**)&axs, g_axs);
    cudaGetSymbolAddress((void**)&aqs, g_aqs);
    cudaGetSymbolAddress((void**)&aos, g_aos);
    cudaGetSymbolAddress((void**)&wq2, g_wq2);
    cudaGetSymbolAddress((void**)&wk2, g_wk2);
    cudaGetSymbolAddress((void**)&wv2, g_wv2);
    cudaGetSymbolAddress((void**)&wp2, g_wp2);
    cudaGetSymbolAddress((void**)&qs, g_qs);
    cudaGetSymbolAddress((void**)&k2, g_k2);
    cudaGetSymbolAddress((void**)&v2, g_v2);
    cudaGetSymbolAddress((void**)&ps, g_ps);

    EncodeTiledFn enc = nullptr;
    {
        void* fn = nullptr;
        cudaDriverEntryPointQueryResult st;
        cudaGetDriverEntryPoint("cuTensorMapEncodeTiled", &fn, cudaEnableDefault, &st);
        enc = (EncodeTiledFn)fn;
    }
    CUtensorMap mAx, mAq, mAo;
    CUtensorMap mWq, mWk, mWv, mWp;
    CUtensorMap mQ, mK, mV, mP;
    make_map(enc, &mAx, axs, C_, (uint64_t)B_ * N_, 64, 128);
    make_map(enc, &mAq, aqs, C_, (uint64_t)B_ * QN, 64, 128);
    make_map(enc, &mAo, aos, C_, (uint64_t)B_ * QN, 64, 128);
    make_map(enc, &mWq, wq2, C_, C_, 64, 128);
    make_map(enc, &mWk, wk2, C_, C_, 64, 128);
    make_map(enc, &mWv, wv2, C_, C_, 64, 128);
    make_map(enc, &mWp, wp2, C_, C_, 64, 128);
    make_map(enc, &mQ,  qs,  HD, (uint64_t)BH * QN, 64, 48);
    make_map(enc, &mK,  k2,  HD, (uint64_t)BH * N_, 64, 96);
    make_map(enc, &mV,  v2,  HD, (uint64_t)BH * N_, 64, 64);
    make_map(enc, &mP,  ps,  N_, (uint64_t)BH * QN, 64, 48);

    cudaFuncSetAttribute(gemm_1t,  cudaFuncAttributeMaxDynamicSharedMemorySize, G1_SMEM);
    cudaFuncSetAttribute(qk_fused, cudaFuncAttributeMaxDynamicSharedMemorySize, QKF_SMEM);
    cudaFuncSetAttribute(av_mma, cudaFuncAttributeMaxDynamicSharedMemorySize, AV_SMEM);

    conv_x_kernel<<<dim3(18, 32, B_), dim3(32, 8)>>>(x);
    split_wT_f16_kernel<<<dim3(32, 32), dim3(32, 8)>>>(Wk, wk2);
    split_wT_f16_kernel<<<dim3(32, 32), dim3(32, 8)>>>(Wv, wv2);
    split_wT_f16_kernel<<<dim3(32, 32), dim3(32, 8)>>>(Wq, wq2);
    split_wT_f16_kernel<<<dim3(32, 32), dim3(32, 8)>>>(Wp, wp2);
    gemm_1t<<<dim3(8, (B_ * N_) / 128, 2), 512, G1_SMEM>>>(mAx, mWk, mWv, k2, v2, nullptr, nullptr, N_, 2);

    pool_kernel<<<dim3(C_ / 16, B_), 256>>>(x);
    gemm_1t<<<dim3(8, (B_ * QN) / 128, 1), 512, G1_SMEM>>>(mAq, mWq, mWq, qs, qs, nullptr, q, QN, 3);

    relpos_kernel<<<BH * QN, 64>>>(rph, rpw);
    qk_fused<<<dim3(1, 3, BH), 576, QKF_SMEM>>>(mQ, mK);
    av_mma<<<dim3(1, 3, BH), 384, AV_SMEM>>>(mP, mV);

    gemm_1t<<<dim3(8, (B_ * QN) / 128, 1), 512, G1_SMEM>>>(mAo, mWp, mWp, nullptr, nullptr, bp, out, QN, 1);
}